// round 3
// baseline (speedup 1.0000x reference)
#include <cuda_runtime.h>
#include <math.h>

__device__ __forceinline__ float2 cmul(float2 a, float2 b) {
    return make_float2(a.x * b.x - a.y * b.y, a.x * b.y + a.y * b.x);
}

// Computes M (3x3) such that z = (1, cosx0, sinx0) . M . (1, cosx1, sinx1)^T
// where z = psi^T S psi, S = Re(U^dag (Z(x)I) U) for the pair-0 circuit.
__device__ void compute_M(const float* __restrict__ params, float* __restrict__ M) {
    float2 U[4][4];
#pragma unroll
    for (int r = 0; r < 4; r++)
#pragma unroll
        for (int c = 0; c < 4; c++)
            U[r][c] = make_float2(r == c ? 1.0f : 0.0f, 0.0f);

#pragma unroll
    for (int layer = 0; layer < 3; layer++) {
        const float* pp = params + layer * 16;  // pair 0 of this layer
        float t0 = pp[0], t1 = pp[1], t2 = pp[2], t3 = pp[3];

        // RZ(t0) on qubit A (row bit 1)
        {
            float ch, sh;
            __sincosf(0.5f * t0, &sh, &ch);
            float2 e0 = make_float2(ch, -sh);
            float2 e1 = make_float2(ch, sh);
#pragma unroll
            for (int r = 0; r < 4; r++) {
                float2 ph = ((r >> 1) & 1) ? e1 : e0;
#pragma unroll
                for (int c = 0; c < 4; c++) U[r][c] = cmul(ph, U[r][c]);
            }
        }
        // RX(t1) on qubit B (row bit 0)
        {
            float ch, sh;
            __sincosf(0.5f * t1, &sh, &ch);
#pragma unroll
            for (int base = 0; base < 4; base += 2) {
#pragma unroll
                for (int c = 0; c < 4; c++) {
                    float2 a = U[base][c], b = U[base + 1][c];
                    float2 misb = make_float2(sh * b.y, -sh * b.x);
                    float2 misa = make_float2(sh * a.y, -sh * a.x);
                    U[base][c]     = make_float2(ch * a.x + misb.x, ch * a.y + misb.y);
                    U[base + 1][c] = make_float2(misa.x + ch * b.x, misa.y + ch * b.y);
                }
            }
        }
        // CNOT(A->B): swap rows 2 and 3
        {
#pragma unroll
            for (int c = 0; c < 4; c++) {
                float2 tmp = U[2][c]; U[2][c] = U[3][c]; U[3][c] = tmp;
            }
        }
        // RZ(t2) on qubit B
        {
            float ch, sh;
            __sincosf(0.5f * t2, &sh, &ch);
            float2 e0 = make_float2(ch, -sh);
            float2 e1 = make_float2(ch, sh);
#pragma unroll
            for (int r = 0; r < 4; r++) {
                float2 ph = (r & 1) ? e1 : e0;
#pragma unroll
                for (int c = 0; c < 4; c++) U[r][c] = cmul(ph, U[r][c]);
            }
        }
        // RX(t3) on qubit B
        {
            float ch, sh;
            __sincosf(0.5f * t3, &sh, &ch);
#pragma unroll
            for (int base = 0; base < 4; base += 2) {
#pragma unroll
                for (int c = 0; c < 4; c++) {
                    float2 a = U[base][c], b = U[base + 1][c];
                    float2 misb = make_float2(sh * b.y, -sh * b.x);
                    float2 misa = make_float2(sh * a.y, -sh * a.x);
                    U[base][c]     = make_float2(ch * a.x + misb.x, ch * a.y + misb.y);
                    U[base + 1][c] = make_float2(misa.x + ch * b.x, misa.y + ch * b.y);
                }
            }
        }
    }

    // S[k][l] = Re( sum_m conj(U[m][k]) z_m U[m][l] ), z=(+1,+1,-1,-1), k=2a+b
    float S[4][4];
#pragma unroll
    for (int k = 0; k < 4; k++)
#pragma unroll
        for (int l = 0; l < 4; l++) {
            float acc = 0.0f;
#pragma unroll
            for (int m = 0; m < 4; m++) {
                float zs = (m < 2) ? 1.0f : -1.0f;
                acc += zs * (U[m][k].x * U[m][l].x + U[m][k].y * U[m][l].y);
            }
            S[k][l] = acc;
        }

    // Half-angle -> full-angle basis change:
    // cos^2(x/2)=(1+C)/2, sin^2=(1-C)/2, cos*sin=S/2
    const float E[2][2][3] = {
        { {0.5f, 0.5f, 0.0f}, {0.0f, 0.0f, 0.5f} },
        { {0.0f, 0.0f, 0.5f}, {0.5f, -0.5f, 0.0f} }
    };

#pragma unroll
    for (int u = 0; u < 3; u++)
#pragma unroll
        for (int v = 0; v < 3; v++) {
            float acc = 0.0f;
#pragma unroll
            for (int a = 0; a < 2; a++)
#pragma unroll
                for (int c = 0; c < 2; c++)
#pragma unroll
                    for (int b = 0; b < 2; b++)
#pragma unroll
                        for (int d = 0; d < 2; d++)
                            acc += S[2 * a + b][2 * c + d] * E[a][c][u] * E[b][d][v];
            M[u * 3 + v] = acc;
        }
}

__device__ __forceinline__ float eval_elem(const float* sM, float x0, float x1) {
    float C0, S0, C1, S1;
    __sincosf(x0, &S0, &C0);
    __sincosf(x1, &S1, &C1);
    float t0 = fmaf(sM[2], S1, fmaf(sM[1], C1, sM[0]));
    float t1 = fmaf(sM[5], S1, fmaf(sM[4], C1, sM[3]));
    float t2 = fmaf(sM[8], S1, fmaf(sM[7], C1, sM[6]));
    float z  = fmaf(t2, S0, fmaf(t1, C0, t0));
    return __fdividef(1.0f, 1.0f + __expf(-z));
}

__global__ void __launch_bounds__(128, 8) qcnn_kernel(
    const float* __restrict__ inputs,   // (B, 8) row-major
    const float* __restrict__ params,   // (48,)
    float* __restrict__ out,            // (B,)
    int n)
{
    __shared__ float sM[9];

    int t = blockIdx.x * blockDim.x + threadIdx.x;
    int b0 = t * 2;

    // Front-batch both independent loads BEFORE the prologue so the DRAM
    // latency is covered by thread 0's compute_M work.
    const float4* in4 = reinterpret_cast<const float4*>(inputs);
    float4 e0 = make_float4(0.f, 0.f, 0.f, 0.f);
    float4 e1 = e0;
    bool valid = (b0 + 1) < n;
    if (valid) {
        e0 = __ldg(in4 + 2 * b0);       // element b0:  x0=.x, x1=.y
        e1 = __ldg(in4 + 2 * b0 + 2);   // element b0+1
    }

    if (threadIdx.x == 0) {
        compute_M(params, sM);
    }
    __syncthreads();

    if (!valid) return;

    float r0 = eval_elem(sM, e0.x, e0.y);
    float r1 = eval_elem(sM, e1.x, e1.y);

    reinterpret_cast<float2*>(out)[t] = make_float2(r0, r1);
}

extern "C" void kernel_launch(void* const* d_in, const int* in_sizes, int n_in,
                              void* d_out, int out_size) {
    const float* inputs = (const float*)d_in[0];
    const float* params = (const float*)d_in[1];
    float* out = (float*)d_out;

    int n = out_size;  // 131072
    int threads = 128;
    int elems_per_block = threads * 2;
    int blocks = (n + elems_per_block - 1) / elems_per_block;  // 512
    qcnn_kernel<<<blocks, threads>>>(inputs, params, out, n);
}